// round 17
// baseline (speedup 1.0000x reference)
#include <cuda_runtime.h>
#include <math_constants.h>
#include <cstdint>
#include <climits>

#define N_PIX   16384
#define DIM     256
#define K_CODES 8192
#define BATCH   16
#define HW      1024

#define ZQ_ELEMS   (BATCH * DIM * HW)
#define IDX_OFF    ZQ_ELEMS
#define LOSS_OFF   (ZQ_ELEMS + N_PIX)

#define TM 128
#define TN 128
#define NT (K_CODES / TN)
#define NKS (DIM / 32)          // 8 k-steps of k32
#define CAP 384

// smem: int8 tiles 128 x 256B
#define GSM_XS    0
#define GSM_ES0   32768
#define GSM_ES1   65536
#define GSM_RM    98304          // 512 ints
#define ZQP 261
#define GSM_SD    133632         // doubles after s_zq region
#define GSM_TOTAL (GSM_SD + 128)

__device__ __align__(16) float  g_xT[(size_t)N_PIX * DIM];
__device__ __align__(16) char   g_x8[(size_t)N_PIX * DIM];
__device__ __align__(16) char   g_e8[(size_t)K_CODES * DIM];
__device__ float    g_t1[N_PIX];
__device__ float    g_sabs[N_PIX];
__device__ unsigned g_amaxx_bits;
__device__ unsigned g_amaxe_bits;
__device__ unsigned g_maxsume_bits;
__device__ float    g_sx, g_se;
__device__ int2     g_cand[(size_t)N_PIX * CAP];
__device__ int      g_cnt[N_PIX];
__device__ double   g_part[4096];

__device__ __forceinline__ void ldsm4(uint32_t r[4], uint32_t saddr) {
    asm volatile("ldmatrix.sync.aligned.m8n8.x4.shared.b16 {%0,%1,%2,%3}, [%4];"
                 : "=r"(r[0]), "=r"(r[1]), "=r"(r[2]), "=r"(r[3]) : "r"(saddr));
}
__device__ __forceinline__ void imma16832(int c[4], const uint32_t a[4],
                                          uint32_t b0, uint32_t b1) {
    asm volatile(
        "mma.sync.aligned.m16n8k32.row.col.s32.s8.s8.s32 "
        "{%0,%1,%2,%3},{%4,%5,%6,%7},{%8,%9},{%0,%1,%2,%3};"
        : "+r"(c[0]), "+r"(c[1]), "+r"(c[2]), "+r"(c[3])
        : "r"(a[0]), "r"(a[1]), "r"(a[2]), "r"(a[3]), "r"(b0), "r"(b1));
}
__device__ __forceinline__ void cpasync16(uint32_t s, const void* g) {
    asm volatile("cp.async.cg.shared.global [%0], [%1], 16;" :: "r"(s), "l"(g));
}
#define CP_COMMIT()  asm volatile("cp.async.commit_group;")
#define CP_WAIT(n)   asm volatile("cp.async.wait_group %0;" :: "n"(n))

__device__ __forceinline__ uint32_t swz8(int row, int ch) {
    return (uint32_t)(row * 256 + ((ch ^ (row & 7)) << 4));
}
__device__ __forceinline__ int q8(float v, float s) {
    int q = __float2int_rn(v * s);
    return max(-127, min(127, q));
}

// ---------------- 0) t1 (exact chain) / sum|x| / max|x| | max|e| ----------------
__global__ void k_pre(const float* __restrict__ hid, const float* __restrict__ emb) {
    __shared__ float sred[256];
    int blk = blockIdx.x, tid = threadIdx.x;
    float amax = 0.0f;
    if (blk < 64) {
        int b  = blk >> 2;
        int hw = (blk & 3) * 256 + tid;
        const float* src = hid + (size_t)b * DIM * HW + hw;
        float t1 = 0.0f, sa = 0.0f;
        for (int c = 0; c < DIM; c++) {
            float v = src[(size_t)c * HW];
            t1 = __fmaf_rn(v, v, t1);
            sa += fabsf(v);
            amax = fmaxf(amax, fabsf(v));
        }
        int n = b * HW + (blk & 3) * 256 + tid;
        g_t1[n]   = t1;
        g_sabs[n] = sa;
        sred[tid] = amax;
        __syncthreads();
        for (int s = 128; s > 0; s >>= 1) {
            if (tid < s) sred[tid] = fmaxf(sred[tid], sred[tid + s]);
            __syncthreads();
        }
        if (tid == 0) atomicMax(&g_amaxx_bits, __float_as_uint(sred[0]));
    } else {
        for (size_t i = (size_t)(blk - 64) * 256 + tid; i < (size_t)K_CODES * DIM;
             i += 128 * 256)
            amax = fmaxf(amax, fabsf(emb[i]));
        sred[tid] = amax;
        __syncthreads();
        for (int s = 128; s > 0; s >>= 1) {
            if (tid < s) sred[tid] = fmaxf(sred[tid], sred[tid + s]);
            __syncthreads();
        }
        if (tid == 0) atomicMax(&g_amaxe_bits, __float_as_uint(sred[0]));
    }
}

// ---------------- 1) scales + zero counters ----------------
__global__ void k_scales() {
    int n = blockIdx.x * blockDim.x + threadIdx.x;
    if (n == 0) {
        g_sx = 127.0f / __uint_as_float(g_amaxx_bits);
        g_se = 127.0f / __uint_as_float(g_amaxe_bits);
    }
    if (n < N_PIX) g_cnt[n] = 0;
}

// ---------------- 2) transpose+quantX | quantE + max sum|e| ----------------
__global__ void k_quant(const float* __restrict__ hid, const float* __restrict__ emb) {
    int blk = blockIdx.x, tid = threadIdx.x;
    if (blk < 4096) {
        __shared__ float s[32][33];
        int b  = blk >> 8;
        int c0 = ((blk >> 5) & 7) * 32;
        int w0 = (blk & 31) * 32;
        int lx = tid & 31, ly = tid >> 5;
        const float sx = g_sx;
        const float* src = hid + (size_t)b * DIM * HW;
        #pragma unroll
        for (int i = 0; i < 4; i++) {
            int c = c0 + ly + i * 8;
            s[ly + i * 8][lx] = src[(size_t)c * HW + w0 + lx];
        }
        __syncthreads();
        #pragma unroll
        for (int i = 0; i < 4; i++) {
            int row = ly + i * 8;
            float v = s[lx][row];
            size_t idx = (size_t)(b * HW + w0 + row) * DIM + c0 + lx;
            g_xT[idx] = v;
            g_x8[idx] = (char)q8(v, sx);
        }
    } else {
        int k = (blk - 4096) * 8 + (tid >> 5);
        int lane = tid & 31;
        const float se = g_se;
        const float4* e4 = (const float4*)(emb + (size_t)k * DIM);
        float4 p0 = e4[lane * 2], p1 = e4[lane * 2 + 1];
        float sa = fabsf(p0.x) + fabsf(p0.y) + fabsf(p0.z) + fabsf(p0.w)
                 + fabsf(p1.x) + fabsf(p1.y) + fabsf(p1.z) + fabsf(p1.w);
        uint32_t u0 = (uint32_t)(q8(p0.x, se) & 0xFF)
                    | ((uint32_t)(q8(p0.y, se) & 0xFF) << 8)
                    | ((uint32_t)(q8(p0.z, se) & 0xFF) << 16)
                    | ((uint32_t)(q8(p0.w, se) & 0xFF) << 24);
        uint32_t u1 = (uint32_t)(q8(p1.x, se) & 0xFF)
                    | ((uint32_t)(q8(p1.y, se) & 0xFF) << 8)
                    | ((uint32_t)(q8(p1.z, se) & 0xFF) << 16)
                    | ((uint32_t)(q8(p1.w, se) & 0xFF) << 24);
        ((uint2*)g_e8)[(size_t)k * 32 + lane] = make_uint2(u0, u1);
        #pragma unroll
        for (int off = 16; off > 0; off >>= 1)
            sa += __shfl_xor_sync(0xffffffffu, sa, off);
        if (lane == 0) atomicMax(&g_maxsume_bits, __float_as_uint(sa));
    }
}

// ---------------- 3) int8 IMMA GEMM + shortlist(est) + rescore + z_q + loss ----------------
__global__ __launch_bounds__(512, 1) void k_gemm(const float* __restrict__ emb,
                                                 float* __restrict__ out) {
    extern __shared__ char sm[];
    const uint32_t sbase = (uint32_t)__cvta_generic_to_shared(sm);
    int* s_rm = (int*)(sm + GSM_RM);

    const int tid = threadIdx.x;
    const int l   = tid & 31;
    const int w   = tid >> 5;
    const int wm  = (w & 3) * 32;
    const int wn  = (w >> 2) * 32;
    const int wg  = w >> 2;
    const int m0  = blockIdx.x * TM;

    s_rm[tid] = INT_MIN;

    // deterministic 2-sided margins for this thread's 4 row-groups
    const float half_code = 0.5f * g_se * __uint_as_float(g_maxsume_bits);
    const float hsx = 0.5f * g_sx;
    int M2[4];
    #pragma unroll
    for (int j = 0; j < 4; j++) {
        int r = wm + (j >> 1) * 16 + (l >> 2) + (j & 1) * 8;
        M2[j] = 2 * (int)ceilf(half_code + hsx * g_sabs[m0 + r] + 1088.0f);
    }

    uint32_t soff[4];
    #pragma unroll
    for (int it = 0; it < 4; it++) {
        int idx = tid + it * 512;
        soff[it] = swz8(idx >> 4, idx & 15);
    }

    {
        const uint4* e0 = (const uint4*)g_e8;
        #pragma unroll
        for (int it = 0; it < 4; it++)
            cpasync16(sbase + GSM_ES0 + soff[it], e0 + tid + it * 512);
        CP_COMMIT();
        const uint4* xs = (const uint4*)(g_x8 + (size_t)m0 * DIM);
        #pragma unroll
        for (int it = 0; it < 4; it++)
            cpasync16(sbase + GSM_XS + soff[it], xs + tid + it * 512);
        CP_COMMIT();
    }

    const int rA0 = wm + (l & 15);
    const int rA1 = rA0 + 16;
    const int hiA = (l >> 4) & 1;
    const int hiB = (l >> 3) & 1;
    const int rBb = wn + (l & 7) + ((l >> 4) & 1) * 8;

    int best[4];
    #pragma unroll
    for (int j = 0; j < 4; j++) best[j] = INT_MIN;

    for (int kt = 0; kt < NT; kt++) {
        __syncthreads();
        if (kt + 1 < NT) {
            uint32_t eb = sbase + (((kt + 1) & 1) ? GSM_ES1 : GSM_ES0);
            const uint4* src = (const uint4*)(g_e8 + (size_t)(kt + 1) * TN * DIM);
            #pragma unroll
            for (int it = 0; it < 4; it++)
                cpasync16(eb + soff[it], src + tid + it * 512);
            CP_COMMIT();
            CP_WAIT(1);
        } else {
            CP_WAIT(0);
        }
        __syncthreads();

        int acc[2][4][4];
        #pragma unroll
        for (int mi = 0; mi < 2; mi++)
            #pragma unroll
            for (int ni = 0; ni < 4; ni++)
                #pragma unroll
                for (int e = 0; e < 4; e++) acc[mi][ni][e] = 0;

        const uint32_t esb = sbase + ((kt & 1) ? GSM_ES1 : GSM_ES0);
        const uint32_t xsb = sbase + GSM_XS;
        #pragma unroll
        for (int ks = 0; ks < NKS; ks++) {
            uint32_t a0[4], a1[4];
            int cA = 2 * ks + hiA;
            ldsm4(a0, xsb + swz8(rA0, cA));
            ldsm4(a1, xsb + swz8(rA1, cA));
            #pragma unroll
            for (int nb = 0; nb < 2; nb++) {
                uint32_t b[4];
                int rB = rBb + nb * 16;
                int cB = 2 * ks + hiB;
                ldsm4(b, esb + swz8(rB, cB));
                imma16832(acc[0][2 * nb + 0], a0, b[0], b[1]);
                imma16832(acc[0][2 * nb + 1], a0, b[2], b[3]);
                imma16832(acc[1][2 * nb + 0], a1, b[0], b[1]);
                imma16832(acc[1][2 * nb + 1], a1, b[2], b[3]);
            }
        }

        int rmax[4];
        #pragma unroll
        for (int j = 0; j < 4; j++) rmax[j] = INT_MIN;
        #pragma unroll
        for (int mi = 0; mi < 2; mi++)
            #pragma unroll
            for (int ni = 0; ni < 4; ni++)
                #pragma unroll
                for (int e = 0; e < 4; e++) {
                    int j = mi * 2 + (e >> 1);
                    rmax[j] = max(rmax[j], acc[mi][ni][e]);
                }
        #pragma unroll
        for (int j = 0; j < 4; j++) {
            rmax[j] = max(rmax[j], __shfl_xor_sync(0xffffffffu, rmax[j], 1));
            rmax[j] = max(rmax[j], __shfl_xor_sync(0xffffffffu, rmax[j], 2));
        }
        #pragma unroll
        for (int j = 0; j < 4; j++) {
            int r = wm + (j >> 1) * 16 + (l >> 2) + (j & 1) * 8;
            int t = rmax[j];
            t = max(t, s_rm[r * 4 + 0]);
            t = max(t, s_rm[r * 4 + 1]);
            t = max(t, s_rm[r * 4 + 2]);
            t = max(t, s_rm[r * 4 + 3]);
            best[j] = max(best[j], t);
        }
        #pragma unroll
        for (int mi = 0; mi < 2; mi++)
            #pragma unroll
            for (int h = 0; h < 2; h++) {
                int j = mi * 2 + h;
                int thr = best[j] - M2[j];
                int r = wm + mi * 16 + (l >> 2) + h * 8;
                int pix = m0 + r;
                #pragma unroll
                for (int ni = 0; ni < 4; ni++)
                    #pragma unroll
                    for (int e1 = 0; e1 < 2; e1++) {
                        int v = acc[mi][ni][h * 2 + e1];
                        if (v >= thr) {
                            int pos = atomicAdd(&g_cnt[pix], 1);
                            if (pos < CAP)
                                g_cand[(size_t)pix * CAP + pos] =
                                    make_int2(kt * TN + wn + ni * 8 + (l & 3) * 2 + e1, v);
                        }
                    }
            }
        if ((l & 3) == 0) {
            #pragma unroll
            for (int j = 0; j < 4; j++) {
                int r = wm + (j >> 1) * 16 + (l >> 2) + (j & 1) * 8;
                s_rm[r * 4 + wg] = best[j];
            }
        }
    }

    // ---- tail ----
    __syncthreads();                       // lists + s_rm final
    // snapshot final thresholds BEFORE s_zq overwrites s_rm's smem region
    int thrf[8];
    #pragma unroll
    for (int pi = 0; pi < 8; pi++) {
        int p = w * 8 + pi;
        int fb = max(max(s_rm[p * 4 + 0], s_rm[p * 4 + 1]),
                     max(s_rm[p * 4 + 2], s_rm[p * 4 + 3]));
        int m2p = 2 * (int)ceilf(half_code + hsx * g_sabs[m0 + p] + 1088.0f);
        thrf[pi] = fb - m2p;
    }
    __syncthreads();                       // all snapshots done
    float*  s_zq = (float*)sm;             // [128][ZQP]
    double* sd   = (double*)(sm + GSM_SD);
    float*  out_idx = out + IDX_OFF;

    double lacc = 0.0;
    for (int pi = 0; pi < 8; pi++) {
        int p = w * 8 + pi;
        int g = m0 + p;
        int cnt = g_cnt[g]; if (cnt > CAP) cnt = CAP;
        float t1v = g_t1[g];
        const float4* x = (const float4*)(g_xT + (size_t)g * DIM);
        float bd = CUDART_INF_F;
        int   bk = 0x7fffffff;
        for (int c = l; c < cnt; c += 32) {
            int2 ce = g_cand[(size_t)g * CAP + c];
            if (ce.y < thrf[pi]) continue;           // late filter vs final max
            const float4* e = (const float4*)(emb + (size_t)ce.x * DIM);
            float acc = 0.0f;
            #pragma unroll 16
            for (int i = 0; i < DIM / 4; i++) {
                float4 xv = x[i], ev = e[i];
                acc = __fmaf_rn(xv.x, ev.x, acc);
                acc = __fmaf_rn(xv.y, ev.y, acc);
                acc = __fmaf_rn(xv.z, ev.z, acc);
                acc = __fmaf_rn(xv.w, ev.w, acc);
            }
            float d = __fsub_rn(t1v, 2.0f * acc);
            if (d < bd || (d == bd && ce.x < bk)) { bd = d; bk = ce.x; }
        }
        #pragma unroll
        for (int off = 16; off > 0; off >>= 1) {
            float od = __shfl_down_sync(0xffffffffu, bd, off);
            int   ok = __shfl_down_sync(0xffffffffu, bk, off);
            if (od < bd || (od == bd && ok < bk)) { bd = od; bk = ok; }
        }
        int kk = __shfl_sync(0xffffffffu, bk, 0);
        if (l == 0) out_idx[g] = (float)kk;

        const float4* ev4 = (const float4*)(emb + (size_t)kk * DIM);
        float* zrow = s_zq + p * ZQP;
        #pragma unroll
        for (int i = l; i < DIM / 4; i += 32) {
            float4 ev = ev4[i], hv = x[i];
            float d0 = __fsub_rn(ev.x, hv.x), d1 = __fsub_rn(ev.y, hv.y);
            float d2 = __fsub_rn(ev.z, hv.z), d3 = __fsub_rn(ev.w, hv.w);
            zrow[i * 4 + 0] = __fadd_rn(hv.x, d0);
            zrow[i * 4 + 1] = __fadd_rn(hv.y, d1);
            zrow[i * 4 + 2] = __fadd_rn(hv.z, d2);
            zrow[i * 4 + 3] = __fadd_rn(hv.w, d3);
            lacc += (double)d0 * d0 + (double)d1 * d1
                  + (double)d2 * d2 + (double)d3 * d3;
        }
    }
    #pragma unroll
    for (int off = 16; off > 0; off >>= 1)
        lacc += __shfl_down_sync(0xffffffffu, lacc, off);
    if (l == 0) sd[w] = lacc;
    __syncthreads();

    {
        const int b   = m0 >> 10;
        const int hw0 = m0 & (HW - 1);
        float* dst = out + (size_t)b * DIM * HW + hw0;
        const int p  = tid & 127;
        const int cc = tid >> 7;
        for (int cb = 0; cb < DIM; cb += 4) {
            int c = cb + cc;
            dst[(size_t)c * HW + p] = s_zq[p * ZQP + c];
        }
    }
    if (tid == 0) {
        double a = 0.0;
        for (int i = 0; i < 16; i++) a += sd[i];
        g_part[blockIdx.x] = a;
    }
}

__global__ void k_loss2(float* __restrict__ out_loss) {
    __shared__ double sd[128];
    double a = (threadIdx.x < 128) ? g_part[threadIdx.x] : 0.0;
    sd[threadIdx.x] = a;
    __syncthreads();
    for (int s = 64; s > 0; s >>= 1) {
        if (threadIdx.x < s) sd[threadIdx.x] += sd[threadIdx.x + s];
        __syncthreads();
    }
    if (threadIdx.x == 0)
        out_loss[0] = (float)(1.25 * sd[0] / (double)((size_t)N_PIX * DIM));
}

extern "C" void kernel_launch(void* const* d_in, const int* in_sizes, int n_in,
                              void* d_out, int out_size) {
    const float* hid = (const float*)d_in[0];
    const float* emb = (const float*)d_in[1];
    float* out = (float*)d_out;

    cudaFuncSetAttribute(k_gemm, cudaFuncAttributeMaxDynamicSharedMemorySize, GSM_TOTAL);

    k_pre<<<192, 256>>>(hid, emb);                    // 0
    k_scales<<<64, 256>>>();                          // 1
    k_quant<<<4096 + 1024, 256>>>(hid, emb);          // 2
    k_gemm<<<N_PIX / TM, 512, GSM_TOTAL>>>(emb, out); // 3 <- profiler window
    k_loss2<<<1, 128>>>(out + LOSS_OFF);              // 4
}